// round 3
// baseline (speedup 1.0000x reference)
#include <cuda_runtime.h>
#include <cstdint>
#include <math.h>

// NetSimile on 8 block-diagonal graphs of 512 nodes, dense A[4096,4096] in {0,1}.
// Exploits: block-diagonality (only read 8 diagonal 512x512 blocks), binary
// adjacency (bitset rows, B = M1@A via popcount of AND), tiny per-graph stats.

#define NN 4096
#define GG 8
#define MM 512
#define WW 16   // 512 bits = 16 u32 words per row

__device__ uint32_t g_bits[NN][WW];   // adjacency bitsets (no self bit; diag of A is 0)
__device__ int      g_deg[NN];
__device__ float    g_feat[7][NN];

// ---------------------------------------------------------------------------
// K1: build per-row bitsets of the diagonal block + degree. One warp per row.
// ---------------------------------------------------------------------------
__global__ void k_bits(const float* __restrict__ A) {
    int warp = (blockIdx.x * blockDim.x + threadIdx.x) >> 5;
    int lane = threadIdx.x & 31;
    if (warp >= NN) return;
    int g = warp / MM;
    const float* row = A + (size_t)warp * NN + (size_t)g * MM;
    uint32_t myword = 0;
    int deg = 0;
#pragma unroll
    for (int w = 0; w < WW; w++) {
        float v = row[w * 32 + lane];
        unsigned m = __ballot_sync(0xffffffffu, v != 0.0f);
        deg += __popc(m);
        if (lane == w) myword = m;
    }
    if (lane < WW) g_bits[warp][lane] = myword;
    if (lane == 0) g_deg[warp] = deg;
}

// ---------------------------------------------------------------------------
// K2: per-node features f0,f1,f2,f4,f5,f6. One warp per node, 8 warps/block,
// block's graph bitsets staged in shared (padded to 17 words -> conflict-free).
// ---------------------------------------------------------------------------
__global__ void k_feat() {
    __shared__ uint32_t sbits[MM][WW + 1];
    __shared__ int sdeg[MM];
    int tid = threadIdx.x;
    int node0 = blockIdx.x * 8;          // 8 nodes per block, all in same graph
    int g = node0 / MM;
    int base = g * MM;

    for (int idx = tid; idx < MM * WW; idx += 256) {
        int v = idx >> 4, w = idx & 15;
        sbits[v][w] = g_bits[base + v][w];
    }
    for (int idx = tid; idx < MM; idx += 256) sdeg[idx] = g_deg[base + idx];
    __syncthreads();

    int warpId = tid >> 5, lane = tid & 31;
    int n = node0 + warpId;
    int r = n - base;

    uint32_t m1[WW];
#pragma unroll
    for (int w = 0; w < WW; w++) m1[w] = sbits[r][w];
    m1[r >> 5] |= 1u << (r & 31);        // M1 = A | I (self bit)

    int f4 = 0, sumdeg2 = 0, cnt2 = 0, sumdegn = 0;
    for (int v = lane; v < MM; v += 32) {
        int b = 0;
#pragma unroll
        for (int w = 0; w < WW; w++) b += __popc(m1[w] & sbits[v][w]);
        bool m1b = (m1[v >> 5] >> (v & 31)) & 1u;
        bool m2b = m1b || (b > 0);       // M2 = M1 | (B > 0)
        if (m1b) f4 += b;                // (B * M1) row sum
        if (m2b) { cnt2++; sumdeg2 += sdeg[v]; }
        if (m1b && v != r) sumdegn += sdeg[v];   // neighbors only (A bit)
    }
    f4      = __reduce_add_sync(0xffffffffu, f4);
    sumdeg2 = __reduce_add_sync(0xffffffffu, sumdeg2);
    cnt2    = __reduce_add_sync(0xffffffffu, cnt2);
    sumdegn = __reduce_add_sync(0xffffffffu, sumdegn);

    if (lane == 0) {
        float deg = (float)sdeg[r];
        float f0 = deg;
        float f2 = (deg > 0.f) ? (float)sumdegn / deg : 0.f;
        float f1 = (deg > 1.f) ? 2.0f * ((float)f4 - deg) / (deg * (deg - 1.0f)) : 0.f;
        float f4o = 0.5f * (float)f4;
        float f5 = (float)sumdeg2 - 2.0f * (float)f4;
        float f6 = (float)cnt2 - deg - 1.0f;
        g_feat[0][n] = f0;
        g_feat[1][n] = f1;
        g_feat[2][n] = f2;
        g_feat[4][n] = f4o;
        g_feat[5][n] = f5;
        g_feat[6][n] = f6;
    }
}

// ---------------------------------------------------------------------------
// K3: f3 = scatter_mean of neighbor f1. One warp per node; word k is a
// broadcast load, bit 'lane' selects neighbor (k*32+lane).
// ---------------------------------------------------------------------------
__global__ void k_f3() {
    int warp = (blockIdx.x * blockDim.x + threadIdx.x) >> 5;
    int lane = threadIdx.x & 31;
    if (warp >= NN) return;
    int g = warp / MM;
    int base = g * MM;
    float s = 0.f;
#pragma unroll
    for (int k = 0; k < WW; k++) {
        uint32_t w = g_bits[warp][k];
        if ((w >> lane) & 1u) s += g_feat[1][base + k * 32 + lane];
    }
#pragma unroll
    for (int o = 16; o; o >>= 1) s += __shfl_xor_sync(0xffffffffu, s, o);
    if (lane == 0) {
        float deg = (float)g_deg[warp];
        g_feat[3][warp] = (deg > 0.f) ? s / deg : 0.f;
    }
}

// ---------------------------------------------------------------------------
// K4: per (graph, feature) stats. 56 blocks x 512 threads, one element per
// thread. Median via stable rank counting over float4 broadcast LDS; moments
// in fp64 via warp + shared tree reduction.
// ---------------------------------------------------------------------------
__global__ void __launch_bounds__(512) k_stats(float* __restrict__ out) {
    __shared__ float x[MM];
    __shared__ double red[4][16];
    __shared__ float medv;
    __shared__ double smean;

    int f = blockIdx.x % 7, g = blockIdx.x / 7;
    int tid = threadIdx.x;
    int wid = tid >> 5, lane = tid & 31;

    float xi = g_feat[f][g * MM + tid];
    x[tid] = xi;
    __syncthreads();

    // ---- median: stable rank of xi among all 512 values -------------------
    int rank = 0;
    const float4* xv = (const float4*)x;
#pragma unroll 8
    for (int q = 0; q < MM / 4; q++) {
        float4 v = xv[q];
        int j = q * 4;
        rank += (int)((v.x < xi) | ((v.x == xi) & (j + 0 < tid)));
        rank += (int)((v.y < xi) | ((v.y == xi) & (j + 1 < tid)));
        rank += (int)((v.z < xi) | ((v.z == xi) & (j + 2 < tid)));
        rank += (int)((v.w < xi) | ((v.w == xi) & (j + 3 < tid)));
    }
    if (rank == (MM - 1) / 2) medv = xi;   // exactly one thread matches

    // ---- mean -------------------------------------------------------------
    double s = (double)xi;
#pragma unroll
    for (int o = 16; o; o >>= 1) s += __shfl_xor_sync(0xffffffffu, s, o);
    if (lane == 0) red[0][wid] = s;
    __syncthreads();
    if (tid == 0) {
        double t = 0;
#pragma unroll
        for (int i = 0; i < 16; i++) t += red[0][i];
        smean = t / (double)MM;
    }
    __syncthreads();
    double mean = smean;

    // ---- central moments 2,3,4 ---------------------------------------------
    double c = (double)xi - mean;
    double p = c * c;
    double s2 = p, s3 = p * c, s4 = p * p;
#pragma unroll
    for (int o = 16; o; o >>= 1) {
        s2 += __shfl_xor_sync(0xffffffffu, s2, o);
        s3 += __shfl_xor_sync(0xffffffffu, s3, o);
        s4 += __shfl_xor_sync(0xffffffffu, s4, o);
    }
    if (lane == 0) { red[1][wid] = s2; red[2][wid] = s3; red[3][wid] = s4; }
    __syncthreads();

    if (tid == 0) {
        double t2 = 0, t3 = 0, t4 = 0;
#pragma unroll
        for (int i = 0; i < 16; i++) { t2 += red[1][i]; t3 += red[2][i]; t4 += red[3][i]; }
        double m2 = t2 / (double)MM, m3 = t3 / (double)MM, m4 = t4 / (double)MM;
        double eps = 1e-4;
        out[g * 35 + 0  + f] = (float)smean;
        out[g * 35 + 7  + f] = medv;
        out[g * 35 + 14 + f] = (float)sqrt(m2);
        out[g * 35 + 21 + f] = (float)(m3 / fmax(pow(m2, 1.5), eps));
        out[g * 35 + 28 + f] = (float)(m4 / fmax(m2 * m2, eps));
    }
}

extern "C" void kernel_launch(void* const* d_in, const int* in_sizes, int n_in,
                              void* d_out, int out_size) {
    const float* A = (const float*)d_in[0];
    float* out = (float*)d_out;

    k_bits<<<NN / 8, 256>>>(A);          // 4096 warps
    k_feat<<<NN / 8, 256>>>();           // 8 warps/block, 8 nodes/block
    k_f3<<<NN / 8, 256>>>();
    k_stats<<<GG * 7, 512>>>(out);
}

// round 4
// speedup vs baseline: 1.1115x; 1.1115x over previous
#include <cuda_runtime.h>
#include <cstdint>
#include <math.h>

// NetSimile on 8 block-diagonal graphs of 512 nodes, dense A[4096,4096] in {0,1}.
// Exploits: block-diagonality (only read 8 diagonal 512x512 blocks), binary
// adjacency (bitset rows, B = M1@A via popcount of AND), tiny per-graph stats.

#define NN 4096
#define GG 8
#define MM 512
#define WW 16   // 512 bits = 16 u32 words per row

__device__ uint32_t g_bits[NN][WW];   // adjacency bitsets (no self bit; diag of A is 0)
__device__ int      g_deg[NN];
__device__ float    g_feat[7][NN];

// ---------------------------------------------------------------------------
// K1: build per-row bitsets of the diagonal block + degree. One warp per row.
// ---------------------------------------------------------------------------
__global__ void k_bits(const float* __restrict__ A) {
    int warp = (blockIdx.x * blockDim.x + threadIdx.x) >> 5;
    int lane = threadIdx.x & 31;
    if (warp >= NN) return;
    int g = warp / MM;
    const float* row = A + (size_t)warp * NN + (size_t)g * MM;
    uint32_t myword = 0;
    int deg = 0;
#pragma unroll
    for (int w = 0; w < WW; w++) {
        float v = row[w * 32 + lane];
        unsigned m = __ballot_sync(0xffffffffu, v != 0.0f);
        deg += __popc(m);
        if (lane == w) myword = m;
    }
    if (lane < WW) g_bits[warp][lane] = myword;
    if (lane == 0) g_deg[warp] = deg;
}

// ---------------------------------------------------------------------------
// K2: per-node features f0,f1,f2,f4,f5,f6. One warp per node, 8 warps/block,
// block's graph bitsets staged in shared (padded to 17 words -> conflict-free).
// ---------------------------------------------------------------------------
__global__ void k_feat() {
    __shared__ uint32_t sbits[MM][WW + 1];
    __shared__ int sdeg[MM];
    int tid = threadIdx.x;
    int node0 = blockIdx.x * 8;          // 8 nodes per block, all in same graph
    int g = node0 / MM;
    int base = g * MM;

    for (int idx = tid; idx < MM * WW; idx += 256) {
        int v = idx >> 4, w = idx & 15;
        sbits[v][w] = g_bits[base + v][w];
    }
    for (int idx = tid; idx < MM; idx += 256) sdeg[idx] = g_deg[base + idx];
    __syncthreads();

    int warpId = tid >> 5, lane = tid & 31;
    int n = node0 + warpId;
    int r = n - base;

    uint32_t m1[WW];
#pragma unroll
    for (int w = 0; w < WW; w++) m1[w] = sbits[r][w];
    m1[r >> 5] |= 1u << (r & 31);        // M1 = A | I (self bit)

    int f4 = 0, sumdeg2 = 0, cnt2 = 0, sumdegn = 0;
    for (int v = lane; v < MM; v += 32) {
        int b = 0;
#pragma unroll
        for (int w = 0; w < WW; w++) b += __popc(m1[w] & sbits[v][w]);
        bool m1b = (m1[v >> 5] >> (v & 31)) & 1u;
        bool m2b = m1b || (b > 0);       // M2 = M1 | (B > 0)
        if (m1b) f4 += b;                // (B * M1) row sum
        if (m2b) { cnt2++; sumdeg2 += sdeg[v]; }
        if (m1b && v != r) sumdegn += sdeg[v];   // neighbors only (A bit)
    }
    f4      = __reduce_add_sync(0xffffffffu, f4);
    sumdeg2 = __reduce_add_sync(0xffffffffu, sumdeg2);
    cnt2    = __reduce_add_sync(0xffffffffu, cnt2);
    sumdegn = __reduce_add_sync(0xffffffffu, sumdegn);

    if (lane == 0) {
        float deg = (float)sdeg[r];
        float f0 = deg;
        float f2 = (deg > 0.f) ? (float)sumdegn / deg : 0.f;
        float f1 = (deg > 1.f) ? 2.0f * ((float)f4 - deg) / (deg * (deg - 1.0f)) : 0.f;
        float f4o = 0.5f * (float)f4;
        float f5 = (float)sumdeg2 - 2.0f * (float)f4;
        float f6 = (float)cnt2 - deg - 1.0f;
        g_feat[0][n] = f0;
        g_feat[1][n] = f1;
        g_feat[2][n] = f2;
        g_feat[4][n] = f4o;
        g_feat[5][n] = f5;
        g_feat[6][n] = f6;
    }
}

// ---------------------------------------------------------------------------
// K3: f3 = scatter_mean of neighbor f1. One warp per node; word k is a
// broadcast load, bit 'lane' selects neighbor (k*32+lane).
// ---------------------------------------------------------------------------
__global__ void k_f3() {
    int warp = (blockIdx.x * blockDim.x + threadIdx.x) >> 5;
    int lane = threadIdx.x & 31;
    if (warp >= NN) return;
    int g = warp / MM;
    int base = g * MM;
    float s = 0.f;
#pragma unroll
    for (int k = 0; k < WW; k++) {
        uint32_t w = g_bits[warp][k];
        if ((w >> lane) & 1u) s += g_feat[1][base + k * 32 + lane];
    }
#pragma unroll
    for (int o = 16; o; o >>= 1) s += __shfl_xor_sync(0xffffffffu, s, o);
    if (lane == 0) {
        float deg = (float)g_deg[warp];
        g_feat[3][warp] = (deg > 0.f) ? s / deg : 0.f;
    }
}

// ---------------------------------------------------------------------------
// K4: per (graph, feature) stats. 56 blocks x 512 threads, one element per
// thread. Median via stable rank counting over float4 broadcast LDS; moment
// ACCUMULATION in fp64 (parallel shuffle trees only), all serial epilogue
// math in fp32 (no software fp64 pow/div/sqrt on a single thread).
// ---------------------------------------------------------------------------
__global__ void __launch_bounds__(512) k_stats(float* __restrict__ out) {
    __shared__ float x[MM];
    __shared__ double red[4][16];
    __shared__ float medv;
    __shared__ double smean;

    int f = blockIdx.x % 7, g = blockIdx.x / 7;
    int tid = threadIdx.x;
    int wid = tid >> 5, lane = tid & 31;

    float xi = g_feat[f][g * MM + tid];
    x[tid] = xi;

    // ---- mean partials (before barrier; overlap with store) ---------------
    double s = (double)xi;
#pragma unroll
    for (int o = 16; o; o >>= 1) s += __shfl_xor_sync(0xffffffffu, s, o);
    if (lane == 0) red[0][wid] = s;
    __syncthreads();

    // ---- median: stable rank of xi among all 512 values -------------------
    int rank = 0;
    const float4* xv = (const float4*)x;
#pragma unroll 8
    for (int q = 0; q < MM / 4; q++) {
        float4 v = xv[q];
        int j = q * 4;
        rank += (int)((v.x < xi) | ((v.x == xi) & (j + 0 < tid)));
        rank += (int)((v.y < xi) | ((v.y == xi) & (j + 1 < tid)));
        rank += (int)((v.z < xi) | ((v.z == xi) & (j + 2 < tid)));
        rank += (int)((v.w < xi) | ((v.w == xi) & (j + 3 < tid)));
    }
    if (rank == (MM - 1) / 2) medv = xi;   // exactly one thread matches

    // ---- finish mean with warp 0 (parallel, no serial 16-add chain) -------
    if (tid < 32) {
        double t = (lane < 16) ? red[0][lane] : 0.0;
#pragma unroll
        for (int o = 8; o; o >>= 1) t += __shfl_xor_sync(0xffffffffu, t, o);
        if (lane == 0) smean = t * (1.0 / (double)MM);
    }
    __syncthreads();
    float mean = (float)smean;

    // ---- central moments 2,3,4 (fp32 centered, fp64 accumulation) ---------
    double c = (double)(xi - mean);
    double p = c * c;
    double s2 = p, s3 = p * c, s4 = p * p;
#pragma unroll
    for (int o = 16; o; o >>= 1) {
        s2 += __shfl_xor_sync(0xffffffffu, s2, o);
        s3 += __shfl_xor_sync(0xffffffffu, s3, o);
        s4 += __shfl_xor_sync(0xffffffffu, s4, o);
    }
    if (lane == 0) { red[1][wid] = s2; red[2][wid] = s3; red[3][wid] = s4; }
    __syncthreads();

    if (tid < 32) {
        double t2 = (lane < 16) ? red[1][lane] : 0.0;
        double t3 = (lane < 16) ? red[2][lane] : 0.0;
        double t4 = (lane < 16) ? red[3][lane] : 0.0;
#pragma unroll
        for (int o = 8; o; o >>= 1) {
            t2 += __shfl_xor_sync(0xffffffffu, t2, o);
            t3 += __shfl_xor_sync(0xffffffffu, t3, o);
            t4 += __shfl_xor_sync(0xffffffffu, t4, o);
        }
        if (lane == 0) {
            // All remaining math in fp32: sqrtf/div are cheap MUFU+Newton.
            float m2 = (float)(t2 * (1.0 / (double)MM));
            float m3 = (float)(t3 * (1.0 / (double)MM));
            float m4 = (float)(t4 * (1.0 / (double)MM));
            float eps = 1e-4f;
            float sq = sqrtf(m2);
            out[g * 35 + 0  + f] = (float)smean;
            out[g * 35 + 7  + f] = medv;
            out[g * 35 + 14 + f] = sq;
            out[g * 35 + 21 + f] = m3 / fmaxf(m2 * sq, eps);
            out[g * 35 + 28 + f] = m4 / fmaxf(m2 * m2, eps);
        }
    }
}

extern "C" void kernel_launch(void* const* d_in, const int* in_sizes, int n_in,
                              void* d_out, int out_size) {
    const float* A = (const float*)d_in[0];
    float* out = (float*)d_out;

    k_bits<<<NN / 8, 256>>>(A);          // 4096 warps
    k_feat<<<NN / 8, 256>>>();           // 8 warps/block, 8 nodes/block
    k_f3<<<NN / 8, 256>>>();
    k_stats<<<GG * 7, 512>>>(out);
}

// round 5
// speedup vs baseline: 1.3714x; 1.2339x over previous
#include <cuda_runtime.h>
#include <cstdint>
#include <math.h>

// NetSimile on 8 block-diagonal graphs of 512 nodes, dense A[4096,4096] in {0,1}.
// Exploits: block-diagonality (only read 8 diagonal 512x512 blocks), binary
// adjacency (bitset rows, B = M1@A via popcount of AND), tiny per-graph stats.

#define NN 4096
#define GG 8
#define MM 512
#define WW 16   // 512 bits = 16 u32 words per row

__device__ uint32_t g_bits[NN][WW];   // adjacency bitsets (no self bit; diag of A is 0)
__device__ int      g_deg[NN];
__device__ float    g_feat[7][NN];

// ---------------------------------------------------------------------------
// K1: build per-row bitsets of the diagonal block + degree. One warp per row.
// ---------------------------------------------------------------------------
__global__ void k_bits(const float* __restrict__ A) {
    int warp = (blockIdx.x * blockDim.x + threadIdx.x) >> 5;
    int lane = threadIdx.x & 31;
    if (warp >= NN) return;
    int g = warp / MM;
    const float* row = A + (size_t)warp * NN + (size_t)g * MM;
    uint32_t myword = 0;
    int deg = 0;
#pragma unroll
    for (int w = 0; w < WW; w++) {
        float v = row[w * 32 + lane];
        unsigned m = __ballot_sync(0xffffffffu, v != 0.0f);
        deg += __popc(m);
        if (lane == w) myword = m;
    }
    if (lane < WW) g_bits[warp][lane] = myword;
    if (lane == 0) g_deg[warp] = deg;
}

// ---------------------------------------------------------------------------
// K2: per-node features f0,f1,f2,f4,f5,f6. One warp per node, 8 warps/block,
// block's graph bitsets staged in shared (padded to 17 words -> conflict-free).
// ---------------------------------------------------------------------------
__global__ void k_feat() {
    __shared__ uint32_t sbits[MM][WW + 1];
    __shared__ int sdeg[MM];
    int tid = threadIdx.x;
    int node0 = blockIdx.x * 8;          // 8 nodes per block, all in same graph
    int g = node0 / MM;
    int base = g * MM;

    for (int idx = tid; idx < MM * WW; idx += 256) {
        int v = idx >> 4, w = idx & 15;
        sbits[v][w] = g_bits[base + v][w];
    }
    for (int idx = tid; idx < MM; idx += 256) sdeg[idx] = g_deg[base + idx];
    __syncthreads();

    int warpId = tid >> 5, lane = tid & 31;
    int n = node0 + warpId;
    int r = n - base;

    uint32_t m1[WW];
#pragma unroll
    for (int w = 0; w < WW; w++) m1[w] = sbits[r][w];
    m1[r >> 5] |= 1u << (r & 31);        // M1 = A | I (self bit)

    int f4 = 0, sumdeg2 = 0, cnt2 = 0, sumdegn = 0;
    for (int v = lane; v < MM; v += 32) {
        int b = 0;
#pragma unroll
        for (int w = 0; w < WW; w++) b += __popc(m1[w] & sbits[v][w]);
        bool m1b = (m1[v >> 5] >> (v & 31)) & 1u;
        bool m2b = m1b || (b > 0);       // M2 = M1 | (B > 0)
        if (m1b) f4 += b;                // (B * M1) row sum
        if (m2b) { cnt2++; sumdeg2 += sdeg[v]; }
        if (m1b && v != r) sumdegn += sdeg[v];   // neighbors only (A bit)
    }
    f4      = __reduce_add_sync(0xffffffffu, f4);
    sumdeg2 = __reduce_add_sync(0xffffffffu, sumdeg2);
    cnt2    = __reduce_add_sync(0xffffffffu, cnt2);
    sumdegn = __reduce_add_sync(0xffffffffu, sumdegn);

    if (lane == 0) {
        float deg = (float)sdeg[r];
        float f0 = deg;
        float f2 = (deg > 0.f) ? (float)sumdegn / deg : 0.f;
        float f1 = (deg > 1.f) ? 2.0f * ((float)f4 - deg) / (deg * (deg - 1.0f)) : 0.f;
        float f4o = 0.5f * (float)f4;
        float f5 = (float)sumdeg2 - 2.0f * (float)f4;
        float f6 = (float)cnt2 - deg - 1.0f;
        g_feat[0][n] = f0;
        g_feat[1][n] = f1;
        g_feat[2][n] = f2;
        g_feat[4][n] = f4o;
        g_feat[5][n] = f5;
        g_feat[6][n] = f6;
    }
}

// ---------------------------------------------------------------------------
// K3: f3 = scatter_mean of neighbor f1. One warp per node; word k is a
// broadcast load, bit 'lane' selects neighbor (k*32+lane).
// ---------------------------------------------------------------------------
__global__ void k_f3() {
    int warp = (blockIdx.x * blockDim.x + threadIdx.x) >> 5;
    int lane = threadIdx.x & 31;
    if (warp >= NN) return;
    int g = warp / MM;
    int base = g * MM;
    float s = 0.f;
#pragma unroll
    for (int k = 0; k < WW; k++) {
        uint32_t w = g_bits[warp][k];
        if ((w >> lane) & 1u) s += g_feat[1][base + k * 32 + lane];
    }
#pragma unroll
    for (int o = 16; o; o >>= 1) s += __shfl_xor_sync(0xffffffffu, s, o);
    if (lane == 0) {
        float deg = (float)g_deg[warp];
        g_feat[3][warp] = (deg > 0.f) ? s / deg : 0.f;
    }
}

// ---------------------------------------------------------------------------
// K4: per (graph, feature) stats. 56 blocks x 512 threads, one element per
// thread. Median via 4-pass 8-bit MSB radix select (O(M) vs O(M^2) rank
// counting); moments accumulated in fp64 shuffle trees, fp32 epilogue.
// Invariant per pass: histogram counts candidates whose high bits == pref;
// k is the target rank WITHIN that candidate set; after selecting bin b with
// sel_below candidates in lower bins, new candidates = bin b, new k -= sel_below.
// ---------------------------------------------------------------------------
__global__ void __launch_bounds__(512) k_stats(float* __restrict__ out) {
    __shared__ int hist[256];
    __shared__ double red[4][16];
    __shared__ double smean;
    __shared__ int sel_bin, sel_below;

    int f = blockIdx.x % 7, g = blockIdx.x / 7;
    int tid = threadIdx.x;
    int wid = tid >> 5, lane = tid & 31;

    float xi = g_feat[f][g * MM + tid];

    // ---- mean partials ----------------------------------------------------
    double s = (double)xi;
#pragma unroll
    for (int o = 16; o; o >>= 1) s += __shfl_xor_sync(0xffffffffu, s, o);
    if (lane == 0) red[0][wid] = s;

    // ---- median: radix select of rank-255 element -------------------------
    uint32_t bits = __float_as_uint(xi);
    uint32_t key = (bits & 0x80000000u) ? ~bits : (bits ^ 0x80000000u);

    int k = (MM - 1) / 2;   // 255
    uint32_t pref = 0;      // selected bits above (shift+8)
#pragma unroll
    for (int shift = 24; shift >= 0; shift -= 8) {
        if (tid < 256) hist[tid] = 0;
        __syncthreads();
        bool active = (shift == 24) || ((key >> (shift + 8)) == pref);
        if (active) atomicAdd(&hist[(key >> shift) & 255], 1);
        __syncthreads();
        if (tid < 32) {
            int c[8];
            int t = 0;
#pragma unroll
            for (int j = 0; j < 8; j++) { c[j] = hist[lane * 8 + j]; t += c[j]; }
            int pscan = t;
#pragma unroll
            for (int o = 1; o < 32; o <<= 1) {
                int v = __shfl_up_sync(0xffffffffu, pscan, o);
                if (lane >= o) pscan += v;
            }
            int before_lane = pscan - t;
            if (k >= before_lane && k < before_lane + t) {
                int kk = k - before_lane;
                int below = before_lane;
#pragma unroll
                for (int j = 0; j < 8; j++) {
                    if (kk >= c[j]) { kk -= c[j]; below += c[j]; }
                    else { sel_bin = lane * 8 + j; sel_below = below; break; }
                }
            }
        }
        __syncthreads();
        pref = (pref << 8) | (uint32_t)sel_bin;
        k -= sel_below;                    // rank within the selected bin
        __syncthreads();
    }
    uint32_t medkey = pref;                // full 32-bit key of the median
    uint32_t mb = (medkey & 0x80000000u) ? (medkey ^ 0x80000000u) : ~medkey;
    float medv = __uint_as_float(mb);

    // ---- finish mean with warp 0 ------------------------------------------
    if (tid < 32) {
        double t = (lane < 16) ? red[0][lane] : 0.0;
#pragma unroll
        for (int o = 8; o; o >>= 1) t += __shfl_xor_sync(0xffffffffu, t, o);
        if (lane == 0) smean = t * (1.0 / (double)MM);
    }
    __syncthreads();
    float mean = (float)smean;

    // ---- central moments 2,3,4 (fp32 centered, fp64 accumulation) ---------
    double c = (double)(xi - mean);
    double p = c * c;
    double s2 = p, s3 = p * c, s4 = p * p;
#pragma unroll
    for (int o = 16; o; o >>= 1) {
        s2 += __shfl_xor_sync(0xffffffffu, s2, o);
        s3 += __shfl_xor_sync(0xffffffffu, s3, o);
        s4 += __shfl_xor_sync(0xffffffffu, s4, o);
    }
    if (lane == 0) { red[1][wid] = s2; red[2][wid] = s3; red[3][wid] = s4; }
    __syncthreads();

    if (tid < 32) {
        double t2 = (lane < 16) ? red[1][lane] : 0.0;
        double t3 = (lane < 16) ? red[2][lane] : 0.0;
        double t4 = (lane < 16) ? red[3][lane] : 0.0;
#pragma unroll
        for (int o = 8; o; o >>= 1) {
            t2 += __shfl_xor_sync(0xffffffffu, t2, o);
            t3 += __shfl_xor_sync(0xffffffffu, t3, o);
            t4 += __shfl_xor_sync(0xffffffffu, t4, o);
        }
        if (lane == 0) {
            float m2 = (float)(t2 * (1.0 / (double)MM));
            float m3 = (float)(t3 * (1.0 / (double)MM));
            float m4 = (float)(t4 * (1.0 / (double)MM));
            float eps = 1e-4f;
            float sq = sqrtf(m2);
            out[g * 35 + 0  + f] = (float)smean;
            out[g * 35 + 7  + f] = medv;
            out[g * 35 + 14 + f] = sq;
            out[g * 35 + 21 + f] = m3 / fmaxf(m2 * sq, eps);
            out[g * 35 + 28 + f] = m4 / fmaxf(m2 * m2, eps);
        }
    }
}

extern "C" void kernel_launch(void* const* d_in, const int* in_sizes, int n_in,
                              void* d_out, int out_size) {
    const float* A = (const float*)d_in[0];
    float* out = (float*)d_out;

    k_bits<<<NN / 8, 256>>>(A);          // 4096 warps
    k_feat<<<NN / 8, 256>>>();           // 8 warps/block, 8 nodes/block
    k_f3<<<NN / 8, 256>>>();
    k_stats<<<GG * 7, 512>>>(out);
}